// round 4
// baseline (speedup 1.0000x reference)
#include <cuda_runtime.h>
#include <cstdint>

// Circular convolution of 8192 rows of length 4096 via packed-real FFT,
// two rows per CTA. Radix-16 Stockham, 3 stages, 256 threads.
// Forward FFTs use a sigma-relabeled stage-0 exchange so the stage-1
// exchange becomes an intra-half-warp 16x16 register transpose (shfl only).
// Inverse keeps smem for its stage-1 exchange so output stores coalesce.
// 13 smem passes + 7 barriers per 2 rows (was 17 + 11).

#define NFFT 4096
#define NT 256
#define BUFSZ 4416

__device__ __forceinline__ int P1(int i) { return i + (i >> 4); }
__device__ __forceinline__ int P3(int i) { return i + (i >> 4) + 3 * (i >> 8); }

__device__ __forceinline__ float2 cadd(float2 a, float2 b) { return make_float2(a.x + b.x, a.y + b.y); }
__device__ __forceinline__ float2 csub(float2 a, float2 b) { return make_float2(a.x - b.x, a.y - b.y); }
__device__ __forceinline__ float2 cmul(float2 a, float2 b) {
    return make_float2(fmaf(a.x, b.x, -a.y * b.y), fmaf(a.x, b.y, a.y * b.x));
}

template <int S>
__device__ __forceinline__ float2 mul_iS(float2 a) {
    return make_float2(-(float)S * a.y, (float)S * a.x);
}

template <int S>
__device__ __forceinline__ void dft8(float2 v[8]) {
    const float r2 = 0.70710678118654752440f;
    float2 u0 = cadd(v[0], v[4]), d0 = csub(v[0], v[4]);
    float2 u1 = cadd(v[1], v[5]), d1 = csub(v[1], v[5]);
    float2 u2 = cadd(v[2], v[6]), d2 = csub(v[2], v[6]);
    float2 u3 = cadd(v[3], v[7]), d3 = csub(v[3], v[7]);
    float2 e1 = make_float2((d1.x - (float)S * d1.y) * r2, (d1.y + (float)S * d1.x) * r2);
    float2 e2 = mul_iS<S>(d2);
    float2 e3 = make_float2((-d3.x - (float)S * d3.y) * r2, (-d3.y + (float)S * d3.x) * r2);

    float2 p0 = cadd(u0, u2), p1 = cadd(u1, u3);
    float2 q0 = csub(u0, u2), q1 = mul_iS<S>(csub(u1, u3));
    v[0] = cadd(p0, p1); v[2] = cadd(q0, q1);
    v[4] = csub(p0, p1); v[6] = csub(q0, q1);

    float2 P0 = cadd(d0, e2), P1v = cadd(e1, e3);
    float2 Q0 = csub(d0, e2), Q1 = mul_iS<S>(csub(e1, e3));
    v[1] = cadd(P0, P1v); v[3] = cadd(Q0, Q1);
    v[5] = csub(P0, P1v); v[7] = csub(Q0, Q1);
}

template <int S>
__device__ __forceinline__ void dft16(float2 v[16]) {
    float2 e[8], o[8];
    #pragma unroll
    for (int j = 0; j < 8; ++j) { e[j] = v[2 * j]; o[j] = v[2 * j + 1]; }
    dft8<S>(e);
    dft8<S>(o);
    const float COS16[8] = {1.f, 0.9238795325f, 0.7071067812f, 0.3826834324f,
                            0.f, -0.3826834324f, -0.7071067812f, -0.9238795325f};
    const float SIN16[8] = {0.f, 0.3826834324f, 0.7071067812f, 0.9238795325f,
                            1.f, 0.9238795325f, 0.7071067812f, 0.3826834324f};
    #pragma unroll
    for (int k = 0; k < 8; ++k) {
        float2 w = make_float2(COS16[k], (float)S * SIN16[k]);
        float2 t = cmul(o[k], w);
        v[k] = cadd(e[k], t);
        v[k + 8] = csub(e[k], t);
    }
}

template <int S>
__device__ __forceinline__ void twiddle16(float2 v[16], int p, float ninv) {
    float th = (float)S * 6.28318530717958647692f * (float)p * ninv;
    float s1, c1; __sincosf(th, &s1, &c1);
    float s8, c8; __sincosf(8.0f * th, &s8, &c8);
    float2 w1 = make_float2(c1, s1);
    float2 w8 = make_float2(c8, s8);
    v[1] = cmul(v[1], w1);
    float2 wr = w1;
    #pragma unroll
    for (int r = 2; r < 8; ++r) { wr = cmul(wr, w1); v[r] = cmul(v[r], wr); }
    v[8] = cmul(v[8], w8);
    wr = w8;
    #pragma unroll
    for (int r = 9; r < 16; ++r) { wr = cmul(wr, w1); v[r] = cmul(v[r], wr); }
}

// 16x16 transpose of v across the 16 lanes of a half-warp (bits 0..3 of lane
// id). Levels b=8,4,2,1: conditional block swap (l,r) <-> (l^b, r^b).
__device__ __forceinline__ void transpose16(float2 v[16], int lane) {
    #pragma unroll
    for (int b = 8; b >= 1; b >>= 1) {
        const bool upper = (lane & b) != 0;
        #pragma unroll
        for (int r0 = 0; r0 < 16; ++r0) {
            if (r0 & b) continue;           // handle pair (r0, r0|b) once
            const int r1 = r0 | b;
            float2 send = upper ? v[r0] : v[r1];
            float2 recv;
            recv.x = __shfl_xor_sync(0xFFFFFFFFu, send.x, b, 32);
            recv.y = __shfl_xor_sync(0xFFFFFFFFu, send.y, b, 32);
            if (upper) v[r0] = recv; else v[r1] = recv;
        }
    }
}

// Forward FFT given input in regs (v[r] = x[t + 256r]).
// Output: v[r] = X[sig + 256r] where sig = ((t&15)<<4)|(t>>4).
// Uses buf for one smem exchange; presync before the write if buf was
// previously read by other threads.
__device__ __forceinline__ void fwd_fft(float2 v[16], float2* buf, int t, int sig,
                                        bool presync) {
    dft16<-1>(v);
    twiddle16<-1>(v, t, 1.0f / 4096.0f);
    if (presync) __syncthreads();
    #pragma unroll
    for (int r = 0; r < 16; ++r) buf[P1(16 * t + r)] = v[r];
    __syncthreads();
    #pragma unroll
    for (int r = 0; r < 16; ++r) v[r] = buf[P1(sig + NT * r)];
    dft16<-1>(v);
    twiddle16<-1>(v, t & 15, 1.0f / 256.0f);
    transpose16(v, t & 15);
    dft16<-1>(v);
}

extern __shared__ float2 g_smem[];

__global__ void __launch_bounds__(NT, 2)
circconv3_kernel(const float* __restrict__ A, const float* __restrict__ B,
                 float* __restrict__ out) {
    float2* bufA = g_smem;
    float2* bufB = g_smem + BUFSZ;

    const int t = threadIdx.x;
    const int sig = ((t & 15) << 4) | (t >> 4);
    const size_t row0 = 2 * (size_t)blockIdx.x;
    const float* a1 = A + row0 * NFFT;
    const float* a2 = a1 + NFFT;
    const float* b1 = B + row0 * NFFT;
    const float* b2 = b1 + NFFT;

    float2 v[16];

    // ---- forward FFT of z1 = a1 + i*a2 ----
    #pragma unroll
    for (int r = 0; r < 16; ++r) {
        const int k = t + NT * r;
        v[r] = make_float2(a1[k], a2[k]);
    }
    fwd_fft(v, bufA, t, sig, false);   // Z1[sig + 256r] in regs

    // Store Z1 spectrum to bufB (fresh buffer, no hazard)
    #pragma unroll
    for (int r = 0; r < 16; ++r) bufB[P1(sig + NT * r)] = v[r];

    // ---- forward FFT of z2 = b1 + i*b2 ----
    #pragma unroll
    for (int r = 0; r < 16; ++r) {
        const int k = t + NT * r;
        v[r] = make_float2(b1[k], b2[k]);
    }
    fwd_fft(v, bufA, t, sig, true);    // presync: bufA E1 reads outstanding

    // Store Z2 to bufA. Each thread overwrites exactly the slots it just
    // read (own sigma set) -> no cross-thread hazard, no barrier needed.
    #pragma unroll
    for (int r = 0; r < 16; ++r) bufA[P1(sig + NT * r)] = v[r];
    __syncthreads();  // Z1 (bufB) and Z2 (bufA) visible to all

    // ---- unpack + pointwise multiply ----
    // A1=(Z1k+conj(Z1n))/2, A2=-i(Z1k-conj(Z1n))/2, similarly B from Z2.
    // C = A1*B1 + i*(A2*B2); thread owns k = sig + 256r, has Z2k in regs.
    #pragma unroll
    for (int r = 0; r < 16; ++r) {
        const int k = sig + NT * r;
        const int nk = (NFFT - k) & (NFFT - 1);
        const float2 Z2k = v[r];
        const float2 Z1k = bufB[P1(k)];
        const float2 Z1n = bufB[P1(nk)];
        const float2 Z2n = bufA[P1(nk)];
        float2 A1 = make_float2(0.5f * (Z1k.x + Z1n.x), 0.5f * (Z1k.y - Z1n.y));
        float2 A2 = make_float2(0.5f * (Z1k.y + Z1n.y), -0.5f * (Z1k.x - Z1n.x));
        float2 B1 = make_float2(0.5f * (Z2k.x + Z2n.x), 0.5f * (Z2k.y - Z2n.y));
        float2 B2 = make_float2(0.5f * (Z2k.y + Z2n.y), -0.5f * (Z2k.x - Z2n.x));
        float2 C1 = cmul(A1, B1);
        float2 C2 = cmul(A2, B2);
        v[r] = make_float2(C1.x - C2.y, C1.y + C2.x);
    }

    // ---- inverse FFT (owner of C[k] is logical thread sig) ----
    dft16<1>(v);
    twiddle16<1>(v, sig, 1.0f / 4096.0f);
    __syncthreads();  // multiply reads of bufA/bufB complete before overwrite
    #pragma unroll
    for (int r = 0; r < 16; ++r) bufB[P3(16 * sig + r)] = v[r];
    __syncthreads();
    #pragma unroll
    for (int r = 0; r < 16; ++r) v[r] = bufB[P3(t + NT * r)];  // identity relabel

    dft16<1>(v);
    twiddle16<1>(v, t >> 4, 1.0f / 256.0f);
    {
        const int q = t & 15, p = t >> 4;
        #pragma unroll
        for (int r = 0; r < 16; ++r) bufA[P1(q + 256 * p + 16 * r)] = v[r];
    }
    __syncthreads();
    #pragma unroll
    for (int r = 0; r < 16; ++r) v[r] = bufA[P1(t + NT * r)];

    dft16<1>(v);  // time domain, natural order k = t + 256r

    float* o1 = out + row0 * NFFT;
    float* o2 = o1 + NFFT;
    const float inv = 1.0f / (float)NFFT;
    #pragma unroll
    for (int r = 0; r < 16; ++r) {
        const int k = t + NT * r;
        o1[k] = v[r].x * inv;
        o2[k] = v[r].y * inv;
    }
}

extern "C" void kernel_launch(void* const* d_in, const int* in_sizes, int n_in,
                              void* d_out, int out_size) {
    const float* a = (const float*)d_in[0];
    const float* b = (const float*)d_in[1];
    float* out = (float*)d_out;

    const int rows = in_sizes[0] / NFFT;  // 8192
    const int nblocks = rows / 2;         // 4096
    const size_t smem_bytes = 2 * BUFSZ * sizeof(float2);  // 70656 B

    cudaFuncSetAttribute(circconv3_kernel,
                         cudaFuncAttributeMaxDynamicSharedMemorySize,
                         (int)smem_bytes);
    circconv3_kernel<<<nblocks, NT, smem_bytes>>>(a, b, out);
}

// round 5
// speedup vs baseline: 1.0495x; 1.0495x over previous
#include <cuda_runtime.h>
#include <cstdint>

// Circular convolution of 8192 rows of length 4096 via packed-real FFT,
// two rows per CTA (3 complex FFTs per 2 rows). Radix-16 Stockham, 3 stages,
// 256 threads, ping-pong smem. Complex add/sub/scale/rot90 use Blackwell
// packed f32x2 PTX (FFMA2) to halve FMA-pipe instruction count.

#define NFFT 4096
#define NT 256

typedef unsigned long long u64c;

__device__ __forceinline__ int pad(int i) { return i + (i >> 4); }

__device__ __forceinline__ u64c pk2(float x, float y) {
    return ((u64c)__float_as_uint(y) << 32) | (u64c)__float_as_uint(x);
}

// c = a + b (lanewise)
__device__ __forceinline__ float2 cadd(float2 a, float2 b) {
    float2 c;
    asm("{\n\t.reg .b64 ra,rb,rc;\n\t"
        "mov.b64 ra,{%2,%3};\n\tmov.b64 rb,{%4,%5};\n\t"
        "add.rn.f32x2 rc,ra,rb;\n\tmov.b64 {%0,%1},rc;\n\t}"
        : "=f"(c.x), "=f"(c.y)
        : "f"(a.x), "f"(a.y), "f"(b.x), "f"(b.y));
    return c;
}
// c = a - b  (fma: b*(-1) + a)
__device__ __forceinline__ float2 csub(float2 a, float2 b) {
    float2 c;
    asm("{\n\t.reg .b64 ra,rb,rc;\n\t"
        "mov.b64 ra,{%2,%3};\n\tmov.b64 rb,{%4,%5};\n\t"
        "fma.rn.f32x2 rc,rb,%6,ra;\n\tmov.b64 {%0,%1},rc;\n\t}"
        : "=f"(c.x), "=f"(c.y)
        : "f"(a.x), "f"(a.y), "f"(b.x), "f"(b.y),
          "l"(0xBF800000BF800000ULL));
    return c;
}
// c = a * K (lanewise)
__device__ __forceinline__ float2 cscale(float2 a, u64c K) {
    float2 c;
    asm("{\n\t.reg .b64 ra,rc;\n\t"
        "mov.b64 ra,{%2,%3};\n\t"
        "mul.rn.f32x2 rc,ra,%4;\n\tmov.b64 {%0,%1},rc;\n\t}"
        : "=f"(c.x), "=f"(c.y)
        : "f"(a.x), "f"(a.y), "l"(K));
    return c;
}
// c = (a.y*K.lo, a.x*K.hi)
__device__ __forceinline__ float2 cswapmul(float2 a, u64c K) {
    float2 c;
    asm("{\n\t.reg .b64 ra,rc;\n\t"
        "mov.b64 ra,{%3,%2};\n\t"
        "mul.rn.f32x2 rc,ra,%4;\n\tmov.b64 {%0,%1},rc;\n\t}"
        : "=f"(c.x), "=f"(c.y)
        : "f"(a.x), "f"(a.y), "l"(K));
    return c;
}
// c = (a.y*K.lo + c0.x, a.x*K.hi + c0.y)
__device__ __forceinline__ float2 cswapfma(float2 a, u64c K, float2 c0) {
    float2 c;
    asm("{\n\t.reg .b64 ra,rb,rc;\n\t"
        "mov.b64 ra,{%3,%2};\n\tmov.b64 rb,{%4,%5};\n\t"
        "fma.rn.f32x2 rc,ra,%6,rb;\n\tmov.b64 {%0,%1},rc;\n\t}"
        : "=f"(c.x), "=f"(c.y)
        : "f"(a.x), "f"(a.y), "f"(c0.x), "f"(c0.y), "l"(K));
    return c;
}
// c = (a.x*K.lo + c0.x, a.y*K.hi + c0.y)
__device__ __forceinline__ float2 cfma(float2 a, u64c K, float2 c0) {
    float2 c;
    asm("{\n\t.reg .b64 ra,rb,rc;\n\t"
        "mov.b64 ra,{%2,%3};\n\tmov.b64 rb,{%4,%5};\n\t"
        "fma.rn.f32x2 rc,ra,%6,rb;\n\tmov.b64 {%0,%1},rc;\n\t}"
        : "=f"(c.x), "=f"(c.y)
        : "f"(a.x), "f"(a.y), "f"(c0.x), "f"(c0.y), "l"(K));
    return c;
}

// complex multiply (variable operands) — scalar
__device__ __forceinline__ float2 cmul(float2 a, float2 b) {
    return make_float2(fmaf(a.x, b.x, -a.y * b.y), fmaf(a.x, b.y, a.y * b.x));
}
// complex multiply by compile-time constant (wx, wy) — FFMA-imm friendly
__device__ __forceinline__ float2 cmulw(float2 a, float wx, float wy) {
    return make_float2(fmaf(a.x, wx, -a.y * wy), fmaf(a.x, wy, a.y * wx));
}
// a * (i*S)
template <int S>
__device__ __forceinline__ float2 mul_iS(float2 a) {
    return cswapmul(a, pk2(-(float)S, (float)S));
}

template <int S>
__device__ __forceinline__ void dft8(float2 v[8]) {
    const float r2 = 0.70710678118654752440f;
    float2 u0 = cadd(v[0], v[4]), d0 = csub(v[0], v[4]);
    float2 u1 = cadd(v[1], v[5]), d1 = csub(v[1], v[5]);
    float2 u2 = cadd(v[2], v[6]), d2 = csub(v[2], v[6]);
    float2 u3 = cadd(v[3], v[7]), d3 = csub(v[3], v[7]);
    const u64c Kss = pk2(-(float)S * r2, (float)S * r2);
    // e1 = d1 * (1 + iS)/sqrt2
    float2 e1 = cswapfma(d1, Kss, cscale(d1, pk2(r2, r2)));
    // e2 = d2 * iS
    float2 e2 = mul_iS<S>(d2);
    // e3 = d3 * (-1 + iS)/sqrt2
    float2 e3 = cswapfma(d3, Kss, cscale(d3, pk2(-r2, -r2)));

    float2 p0 = cadd(u0, u2), p1 = cadd(u1, u3);
    float2 q0 = csub(u0, u2), q1 = mul_iS<S>(csub(u1, u3));
    v[0] = cadd(p0, p1); v[2] = cadd(q0, q1);
    v[4] = csub(p0, p1); v[6] = csub(q0, q1);

    float2 P0 = cadd(d0, e2), P1 = cadd(e1, e3);
    float2 Q0 = csub(d0, e2), Q1 = mul_iS<S>(csub(e1, e3));
    v[1] = cadd(P0, P1); v[3] = cadd(Q0, Q1);
    v[5] = csub(P0, P1); v[7] = csub(Q0, Q1);
}

template <int S>
__device__ __forceinline__ void dft16(float2 v[16]) {
    float2 e[8], o[8];
    #pragma unroll
    for (int j = 0; j < 8; ++j) { e[j] = v[2 * j]; o[j] = v[2 * j + 1]; }
    dft8<S>(e);
    dft8<S>(o);
    const float C16_1 = 0.92387953251128675613f;
    const float C16_2 = 0.70710678118654752440f;
    const float C16_3 = 0.38268343236508977173f;
    float2 t;
    // k=0: w = 1
    t = o[0];                                 v[0] = cadd(e[0], t); v[8]  = csub(e[0], t);
    t = cmulw(o[1], C16_1, (float)S * C16_3); v[1] = cadd(e[1], t); v[9]  = csub(e[1], t);
    t = cmulw(o[2], C16_2, (float)S * C16_2); v[2] = cadd(e[2], t); v[10] = csub(e[2], t);
    t = cmulw(o[3], C16_3, (float)S * C16_1); v[3] = cadd(e[3], t); v[11] = csub(e[3], t);
    // k=4: w = i*S
    t = mul_iS<S>(o[4]);                      v[4] = cadd(e[4], t); v[12] = csub(e[4], t);
    t = cmulw(o[5], -C16_3, (float)S * C16_1); v[5] = cadd(e[5], t); v[13] = csub(e[5], t);
    t = cmulw(o[6], -C16_2, (float)S * C16_2); v[6] = cadd(e[6], t); v[14] = csub(e[6], t);
    t = cmulw(o[7], -C16_1, (float)S * C16_3); v[7] = cadd(e[7], t); v[15] = csub(e[7], t);
}

template <int S>
__device__ __forceinline__ void twiddle16(float2 v[16], int p, float ninv) {
    float th = (float)S * 6.28318530717958647692f * (float)p * ninv;
    float s1, c1; __sincosf(th, &s1, &c1);
    float s8, c8; __sincosf(8.0f * th, &s8, &c8);
    float2 w1 = make_float2(c1, s1);
    float2 w8 = make_float2(c8, s8);
    v[1] = cmul(v[1], w1);
    float2 wr = w1;
    #pragma unroll
    for (int r = 2; r < 8; ++r) { wr = cmul(wr, w1); v[r] = cmul(v[r], wr); }
    v[8] = cmul(v[8], w8);
    wr = w8;
    #pragma unroll
    for (int r = 9; r < 16; ++r) { wr = cmul(wr, w1); v[r] = cmul(v[r], wr); }
}

// Stage 0 exchange: write 16t+r, read t+256r.
template <int S>
__device__ __forceinline__ void stage0_ex(float2 v[16], float2* buf, int t, bool presync) {
    dft16<S>(v);
    twiddle16<S>(v, t, 1.0f / 4096.0f);
    if (presync) __syncthreads();
    #pragma unroll
    for (int r = 0; r < 16; ++r) buf[pad(16 * t + r)] = v[r];
    __syncthreads();
    #pragma unroll
    for (int r = 0; r < 16; ++r) v[r] = buf[pad(t + NT * r)];
}

// Stage 1 exchange: write q+256p+16r, read t+256r.
template <int S>
__device__ __forceinline__ void stage1_ex(float2 v[16], float2* buf, int t, bool presync) {
    dft16<S>(v);
    twiddle16<S>(v, t >> 4, 1.0f / 256.0f);
    if (presync) __syncthreads();
    const int q = t & 15, p = t >> 4;
    #pragma unroll
    for (int r = 0; r < 16; ++r) buf[pad(q + 256 * p + 16 * r)] = v[r];
    __syncthreads();
    #pragma unroll
    for (int r = 0; r < 16; ++r) v[r] = buf[pad(t + NT * r)];
}

extern __shared__ float2 g_smem[];

__global__ void __launch_bounds__(NT, 2)
circconv4_kernel(const float* __restrict__ A, const float* __restrict__ B,
                 float* __restrict__ out) {
    float2* bufA = g_smem;
    float2* bufB = g_smem + 4352;  // pad(4095)=4350 -> 4352-slot buffers

    const int t = threadIdx.x;
    const size_t row0 = 2 * (size_t)blockIdx.x;
    const float* a1 = A + row0 * NFFT;
    const float* a2 = a1 + NFFT;
    const float* b1 = B + row0 * NFFT;
    const float* b2 = b1 + NFFT;

    float2 v[16];

    // ---- forward FFT of z1 = a1 + i*a2 ----
    #pragma unroll
    for (int r = 0; r < 16; ++r) {
        const int k = t + NT * r;
        v[r] = make_float2(a1[k], a2[k]);
    }
    stage0_ex<-1>(v, bufA, t, false);
    stage1_ex<-1>(v, bufB, t, false);
    dft16<-1>(v);  // Z1 in regs, natural order k = t + 256r

    // Store Z1 spectrum to bufA (bufA stage-0 reads completed before the
    // barrier inside stage1_ex).
    #pragma unroll
    for (int r = 0; r < 16; ++r) bufA[pad(t + NT * r)] = v[r];

    // ---- forward FFT of z2 = b1 + i*b2 (uses bufB only) ----
    #pragma unroll
    for (int r = 0; r < 16; ++r) {
        const int k = t + NT * r;
        v[r] = make_float2(b1[k], b2[k]);
    }
    __syncthreads();  // Z1 store visible; bufB stage-1 reads done
    stage0_ex<-1>(v, bufB, t, false);
    stage1_ex<-1>(v, bufB, t, true);  // presync: bufB reads outstanding
    dft16<-1>(v);  // Z2 in regs

    // Store Z2 spectrum to bufB
    __syncthreads();  // bufB reads from stage1_ex done
    #pragma unroll
    for (int r = 0; r < 16; ++r) bufB[pad(t + NT * r)] = v[r];
    __syncthreads();

    // ---- unpack + pointwise multiply (0.5 factors folded into final scale) ----
    // A1' = Z1k + conj(Z1n)          (2*A1)
    // A2' = (Z1k.y+Z1n.y, Z1n.x-Z1k.x)  (2*A2)
    // likewise B from Z2;  C' = A1'*B1' + i*(A2'*B2')  (= 4*C)
    const u64c K1m1 = pk2(1.0f, -1.0f);
    const u64c Km11 = pk2(-1.0f, 1.0f);
    #pragma unroll
    for (int r = 0; r < 16; ++r) {
        const int k = t + NT * r;
        const int nk = (NFFT - k) & (NFFT - 1);
        const float2 Z2k = v[r];
        const float2 Z1k = bufA[pad(k)];
        const float2 Z1n = bufA[pad(nk)];
        const float2 Z2n = bufB[pad(nk)];
        float2 A1 = cfma(Z1n, K1m1, Z1k);
        float2 A2 = cswapfma(Z1k, K1m1, make_float2(Z1n.y, Z1n.x));
        float2 B1 = cfma(Z2n, K1m1, Z2k);
        float2 B2 = cswapfma(Z2k, K1m1, make_float2(Z2n.y, Z2n.x));
        float2 C1 = cmul(A1, B1);
        float2 C2 = cmul(A2, B2);
        v[r] = cswapfma(C2, Km11, C1);  // (C1.x - C2.y, C1.y + C2.x)
    }

    // ---- inverse FFT of C (already in stage-0 register layout) ----
    stage0_ex<1>(v, bufA, t, true);   // presync: multiply reads outstanding
    stage1_ex<1>(v, bufB, t, false);
    dft16<1>(v);  // time domain: Re = conv(a1,b1), Im = conv(a2,b2)

    float* o1 = out + row0 * NFFT;
    float* o2 = o1 + NFFT;
    const u64c Kinv = pk2(1.0f / 16384.0f, 1.0f / 16384.0f);  // 1/(4*4096)
    #pragma unroll
    for (int r = 0; r < 16; ++r) {
        const int k = t + NT * r;
        float2 w = cscale(v[r], Kinv);
        o1[k] = w.x;
        o2[k] = w.y;
    }
}

extern "C" void kernel_launch(void* const* d_in, const int* in_sizes, int n_in,
                              void* d_out, int out_size) {
    const float* a = (const float*)d_in[0];
    const float* b = (const float*)d_in[1];
    float* out = (float*)d_out;

    const int rows = in_sizes[0] / NFFT;  // 8192
    const int nblocks = rows / 2;         // 4096
    const size_t smem_bytes = 2 * 4352 * sizeof(float2);  // 69632 B

    cudaFuncSetAttribute(circconv4_kernel,
                         cudaFuncAttributeMaxDynamicSharedMemorySize,
                         (int)smem_bytes);
    circconv4_kernel<<<nblocks, NT, smem_bytes>>>(a, b, out);
}

// round 6
// speedup vs baseline: 1.2591x; 1.1997x over previous
#include <cuda_runtime.h>
#include <cstdint>

// Circular convolution of 8192 rows of length 4096 via packed-real FFT,
// two rows per CTA: Z1 = FFT(a1 + i*a2), Z2 = FFT(b1 + i*b2),
// C = A1*B1 + i*A2*B2, one inverse FFT yields both outputs (Re, Im).
// Radix-16 Stockham, 3 stages, 256 threads, ping-pong smem.
// R6: log-depth twiddle tree + cp.async prefetch of the b rows into a third
// smem buffer (overlapped with the first forward FFT).

#define NFFT 4096
#define NT 256

__device__ __forceinline__ int pad(int i) { return i + (i >> 4); }

__device__ __forceinline__ float2 cadd(float2 a, float2 b) { return make_float2(a.x + b.x, a.y + b.y); }
__device__ __forceinline__ float2 csub(float2 a, float2 b) { return make_float2(a.x - b.x, a.y - b.y); }
__device__ __forceinline__ float2 cmul(float2 a, float2 b) {
    return make_float2(fmaf(a.x, b.x, -a.y * b.y), fmaf(a.x, b.y, a.y * b.x));
}
// complex multiply by compile-time constant (FFMA-imm friendly)
__device__ __forceinline__ float2 cmulw(float2 a, float wx, float wy) {
    return make_float2(fmaf(a.x, wx, -a.y * wy), fmaf(a.x, wy, a.y * wx));
}
template <int S>
__device__ __forceinline__ float2 mul_iS(float2 a) {
    return make_float2(-(float)S * a.y, (float)S * a.x);
}

template <int S>
__device__ __forceinline__ void dft8(float2 v[8]) {
    const float r2 = 0.70710678118654752440f;
    float2 u0 = cadd(v[0], v[4]), d0 = csub(v[0], v[4]);
    float2 u1 = cadd(v[1], v[5]), d1 = csub(v[1], v[5]);
    float2 u2 = cadd(v[2], v[6]), d2 = csub(v[2], v[6]);
    float2 u3 = cadd(v[3], v[7]), d3 = csub(v[3], v[7]);
    float2 e1 = make_float2((d1.x - (float)S * d1.y) * r2, (d1.y + (float)S * d1.x) * r2);
    float2 e2 = mul_iS<S>(d2);
    float2 e3 = make_float2((-d3.x - (float)S * d3.y) * r2, (-d3.y + (float)S * d3.x) * r2);

    float2 p0 = cadd(u0, u2), p1 = cadd(u1, u3);
    float2 q0 = csub(u0, u2), q1 = mul_iS<S>(csub(u1, u3));
    v[0] = cadd(p0, p1); v[2] = cadd(q0, q1);
    v[4] = csub(p0, p1); v[6] = csub(q0, q1);

    float2 P0 = cadd(d0, e2), P1 = cadd(e1, e3);
    float2 Q0 = csub(d0, e2), Q1 = mul_iS<S>(csub(e1, e3));
    v[1] = cadd(P0, P1); v[3] = cadd(Q0, Q1);
    v[5] = csub(P0, P1); v[7] = csub(Q0, Q1);
}

template <int S>
__device__ __forceinline__ void dft16(float2 v[16]) {
    float2 e[8], o[8];
    #pragma unroll
    for (int j = 0; j < 8; ++j) { e[j] = v[2 * j]; o[j] = v[2 * j + 1]; }
    dft8<S>(e);
    dft8<S>(o);
    const float C1 = 0.92387953251128675613f;
    const float C2 = 0.70710678118654752440f;
    const float C3 = 0.38268343236508977173f;
    float2 t;
    t = o[0];                               v[0] = cadd(e[0], t); v[8]  = csub(e[0], t);
    t = cmulw(o[1], C1, (float)S * C3);     v[1] = cadd(e[1], t); v[9]  = csub(e[1], t);
    t = cmulw(o[2], C2, (float)S * C2);     v[2] = cadd(e[2], t); v[10] = csub(e[2], t);
    t = cmulw(o[3], C3, (float)S * C1);     v[3] = cadd(e[3], t); v[11] = csub(e[3], t);
    t = mul_iS<S>(o[4]);                    v[4] = cadd(e[4], t); v[12] = csub(e[4], t);
    t = cmulw(o[5], -C3, (float)S * C1);    v[5] = cadd(e[5], t); v[13] = csub(e[5], t);
    t = cmulw(o[6], -C2, (float)S * C2);    v[6] = cadd(e[6], t); v[14] = csub(e[6], t);
    t = cmulw(o[7], -C1, (float)S * C3);    v[7] = cadd(e[7], t); v[15] = csub(e[7], t);
}

// Log-depth twiddle tree: same cmul count as the serial recurrence but
// dependency depth 4 instead of 7.
template <int S>
__device__ __forceinline__ void twiddle16(float2 v[16], int p, float ninv) {
    float th = (float)S * 6.28318530717958647692f * (float)p * ninv;
    float s1, c1; __sincosf(th, &s1, &c1);
    float s8, c8; __sincosf(8.0f * th, &s8, &c8);
    float2 w1 = make_float2(c1, s1);
    float2 w8 = make_float2(c8, s8);
    float2 w2 = cmul(w1, w1);
    v[1] = cmul(v[1], w1);
    v[2] = cmul(v[2], w2);
    float2 w3 = cmul(w2, w1);  v[3] = cmul(v[3], w3);
    float2 w4 = cmul(w2, w2);  v[4] = cmul(v[4], w4);
    float2 w5 = cmul(w3, w2);  v[5] = cmul(v[5], w5);
    float2 w6 = cmul(w4, w2);  v[6] = cmul(v[6], w6);
    float2 w7 = cmul(w5, w2);  v[7] = cmul(v[7], w7);
    v[8] = cmul(v[8], w8);
    float2 w9  = cmul(w8, w1);   v[9]  = cmul(v[9],  w9);
    float2 w10 = cmul(w8, w2);   v[10] = cmul(v[10], w10);
    float2 w11 = cmul(w9, w2);   v[11] = cmul(v[11], w11);
    float2 w12 = cmul(w10, w2);  v[12] = cmul(v[12], w12);
    float2 w13 = cmul(w11, w2);  v[13] = cmul(v[13], w13);
    float2 w14 = cmul(w12, w2);  v[14] = cmul(v[14], w14);
    float2 w15 = cmul(w13, w2);  v[15] = cmul(v[15], w15);
}

// Stage 0 exchange: write 16t+r, read t+256r.
template <int S>
__device__ __forceinline__ void stage0_ex(float2 v[16], float2* buf, int t, bool presync) {
    dft16<S>(v);
    twiddle16<S>(v, t, 1.0f / 4096.0f);
    if (presync) __syncthreads();
    #pragma unroll
    for (int r = 0; r < 16; ++r) buf[pad(16 * t + r)] = v[r];
    __syncthreads();
    #pragma unroll
    for (int r = 0; r < 16; ++r) v[r] = buf[pad(t + NT * r)];
}

// Stage 1 exchange: write q+256p+16r, read t+256r.
template <int S>
__device__ __forceinline__ void stage1_ex(float2 v[16], float2* buf, int t, bool presync) {
    dft16<S>(v);
    twiddle16<S>(v, t >> 4, 1.0f / 256.0f);
    if (presync) __syncthreads();
    const int q = t & 15, p = t >> 4;
    #pragma unroll
    for (int r = 0; r < 16; ++r) buf[pad(q + 256 * p + 16 * r)] = v[r];
    __syncthreads();
    #pragma unroll
    for (int r = 0; r < 16; ++r) v[r] = buf[pad(t + NT * r)];
}

__device__ __forceinline__ void cp_async16(uint32_t saddr, const float* gaddr) {
    asm volatile("cp.async.cg.shared.global [%0], [%1], 16;"
                 :: "r"(saddr), "l"(gaddr));
}

extern __shared__ float2 g_smem[];

__global__ void __launch_bounds__(NT, 2)
circconv6_kernel(const float* __restrict__ A, const float* __restrict__ B,
                 float* __restrict__ out) {
    float2* bufA = g_smem;
    float2* bufB = g_smem + 4352;                 // pad(4095)=4350 -> 4352 slots
    float*  bufC = (float*)(g_smem + 8704);       // 8192 floats: b1 || b2

    const int t = threadIdx.x;
    const size_t row0 = 2 * (size_t)blockIdx.x;
    const float* a1 = A + row0 * NFFT;
    const float* a2 = a1 + NFFT;
    const float* b1 = B + row0 * NFFT;
    const float* b2 = b1 + NFFT;

    float2 v[16];

    // Issue a-loads first (critical path), then prefetch b rows via cp.async.
    #pragma unroll
    for (int r = 0; r < 16; ++r) {
        const int k = t + NT * r;
        v[r] = make_float2(a1[k], a2[k]);
    }

    {
        uint32_t cbase;
        asm("{ .reg .u64 u; cvta.to.shared.u64 u, %1; cvt.u32.u64 %0, u; }"
            : "=r"(cbase) : "l"(bufC));
        #pragma unroll
        for (int j = 0; j < 4; ++j) {
            const int fo = 4 * t + 1024 * j;
            cp_async16(cbase + 4u * fo, b1 + fo);                  // b1 -> bufC[0..4095]
            cp_async16(cbase + 4u * (fo + 4096), b2 + fo);         // b2 -> bufC[4096..]
        }
        asm volatile("cp.async.commit_group;");
    }

    // ---- forward FFT of z1 = a1 + i*a2 ----
    stage0_ex<-1>(v, bufA, t, false);
    stage1_ex<-1>(v, bufB, t, false);
    dft16<-1>(v);  // Z1 in regs, natural order k = t + 256r

    // Store Z1 spectrum to bufA (bufA stage-0 reads completed before the
    // barrier inside stage1_ex).
    #pragma unroll
    for (int r = 0; r < 16; ++r) bufA[pad(t + NT * r)] = v[r];

    // ---- forward FFT of z2 = b1 + i*b2, input from prefetched smem ----
    asm volatile("cp.async.wait_group 0;" ::: "memory");
    __syncthreads();  // Z1 store + everyone's cp.async data visible
    #pragma unroll
    for (int r = 0; r < 16; ++r) {
        const int k = t + NT * r;
        v[r] = make_float2(bufC[k], bufC[k + NFFT]);
    }
    stage0_ex<-1>(v, bufB, t, false);
    stage1_ex<-1>(v, bufB, t, true);  // presync: bufB stage-0 reads outstanding
    dft16<-1>(v);  // Z2 in regs

    // Store Z2 spectrum to bufB
    __syncthreads();  // bufB reads from stage1_ex done
    #pragma unroll
    for (int r = 0; r < 16; ++r) bufB[pad(t + NT * r)] = v[r];
    __syncthreads();

    // ---- unpack + pointwise multiply (0.5 factors folded into final scale) ----
    // A1' = Z1k + conj(Z1n)  (=2*A1);  A2' = (Z1k.y+Z1n.y, Z1n.x-Z1k.x)  (=2*A2)
    // B'  likewise from Z2;  C' = A1'*B1' + i*(A2'*B2')  (= 4*C)
    #pragma unroll
    for (int r = 0; r < 16; ++r) {
        const int k = t + NT * r;
        const int nk = (NFFT - k) & (NFFT - 1);
        const float2 Z2k = v[r];
        const float2 Z1k = bufA[pad(k)];
        const float2 Z1n = bufA[pad(nk)];
        const float2 Z2n = bufB[pad(nk)];
        float2 A1 = make_float2(Z1k.x + Z1n.x, Z1k.y - Z1n.y);
        float2 A2 = make_float2(Z1k.y + Z1n.y, Z1n.x - Z1k.x);
        float2 B1 = make_float2(Z2k.x + Z2n.x, Z2k.y - Z2n.y);
        float2 B2 = make_float2(Z2k.y + Z2n.y, Z2n.x - Z2k.x);
        float2 C1 = cmul(A1, B1);
        float2 C2 = cmul(A2, B2);
        v[r] = make_float2(C1.x - C2.y, C1.y + C2.x);
    }

    // ---- inverse FFT of C (already in stage-0 register layout) ----
    stage0_ex<1>(v, bufA, t, true);   // presync: multiply reads outstanding
    stage1_ex<1>(v, bufB, t, false);
    dft16<1>(v);  // time domain: Re = conv(a1,b1), Im = conv(a2,b2)

    float* o1 = out + row0 * NFFT;
    float* o2 = o1 + NFFT;
    const float inv = 1.0f / 16384.0f;  // 1/(4*4096): unpack halves folded in
    #pragma unroll
    for (int r = 0; r < 16; ++r) {
        const int k = t + NT * r;
        o1[k] = v[r].x * inv;
        o2[k] = v[r].y * inv;
    }
}

extern "C" void kernel_launch(void* const* d_in, const int* in_sizes, int n_in,
                              void* d_out, int out_size) {
    const float* a = (const float*)d_in[0];
    const float* b = (const float*)d_in[1];
    float* out = (float*)d_out;

    const int rows = in_sizes[0] / NFFT;  // 8192
    const int nblocks = rows / 2;         // 4096
    // 2 * 4352 float2 (ping-pong) + 8192 float (b prefetch) = 102400 B
    const size_t smem_bytes = 2 * 4352 * sizeof(float2) + 8192 * sizeof(float);

    cudaFuncSetAttribute(circconv6_kernel,
                         cudaFuncAttributeMaxDynamicSharedMemorySize,
                         (int)smem_bytes);
    circconv6_kernel<<<nblocks, NT, smem_bytes>>>(a, b, out);
}

// round 7
// speedup vs baseline: 1.3210x; 1.0492x over previous
#include <cuda_runtime.h>
#include <cstdint>

// Circular convolution of 8192 rows of length 4096 via packed-real FFT,
// two rows per CTA: Z1 = FFT(a1 + i*a2), Z2 = FFT(b1 + i*b2),
// C = A1*B1 + i*A2*B2, one inverse FFT yields both outputs (Re, Im).
// Radix-16 Stockham, 3 stages, 256 threads.
// R7: 3-buffer choreography (no pre-write barriers anywhere, 8 syncs total),
// float4 stage-0 stores with pad i+2*(i>>4), stage-1 exchanges unpadded,
// Z2 stored via own-slot overwrite (no sync), cp.async b-row prefetch.

#define NFFT 4096
#define NT 256

// padded float2 slot index for stage-0 patterns
__device__ __forceinline__ int p2(int i) { return i + 2 * (i >> 4); }

__device__ __forceinline__ float2 cadd(float2 a, float2 b) { return make_float2(a.x + b.x, a.y + b.y); }
__device__ __forceinline__ float2 csub(float2 a, float2 b) { return make_float2(a.x - b.x, a.y - b.y); }
__device__ __forceinline__ float2 cmul(float2 a, float2 b) {
    return make_float2(fmaf(a.x, b.x, -a.y * b.y), fmaf(a.x, b.y, a.y * b.x));
}
// complex multiply by compile-time constant (FFMA-imm friendly)
__device__ __forceinline__ float2 cmulw(float2 a, float wx, float wy) {
    return make_float2(fmaf(a.x, wx, -a.y * wy), fmaf(a.x, wy, a.y * wx));
}
template <int S>
__device__ __forceinline__ float2 mul_iS(float2 a) {
    return make_float2(-(float)S * a.y, (float)S * a.x);
}

template <int S>
__device__ __forceinline__ void dft8(float2 v[8]) {
    const float r2 = 0.70710678118654752440f;
    float2 u0 = cadd(v[0], v[4]), d0 = csub(v[0], v[4]);
    float2 u1 = cadd(v[1], v[5]), d1 = csub(v[1], v[5]);
    float2 u2 = cadd(v[2], v[6]), d2 = csub(v[2], v[6]);
    float2 u3 = cadd(v[3], v[7]), d3 = csub(v[3], v[7]);
    float2 e1 = make_float2((d1.x - (float)S * d1.y) * r2, (d1.y + (float)S * d1.x) * r2);
    float2 e2 = mul_iS<S>(d2);
    float2 e3 = make_float2((-d3.x - (float)S * d3.y) * r2, (-d3.y + (float)S * d3.x) * r2);

    float2 p0 = cadd(u0, u2), p1 = cadd(u1, u3);
    float2 q0 = csub(u0, u2), q1 = mul_iS<S>(csub(u1, u3));
    v[0] = cadd(p0, p1); v[2] = cadd(q0, q1);
    v[4] = csub(p0, p1); v[6] = csub(q0, q1);

    float2 P0 = cadd(d0, e2), P1 = cadd(e1, e3);
    float2 Q0 = csub(d0, e2), Q1 = mul_iS<S>(csub(e1, e3));
    v[1] = cadd(P0, P1); v[3] = cadd(Q0, Q1);
    v[5] = csub(P0, P1); v[7] = csub(Q0, Q1);
}

template <int S>
__device__ __forceinline__ void dft16(float2 v[16]) {
    float2 e[8], o[8];
    #pragma unroll
    for (int j = 0; j < 8; ++j) { e[j] = v[2 * j]; o[j] = v[2 * j + 1]; }
    dft8<S>(e);
    dft8<S>(o);
    const float C1 = 0.92387953251128675613f;
    const float C2 = 0.70710678118654752440f;
    const float C3 = 0.38268343236508977173f;
    float2 t;
    t = o[0];                               v[0] = cadd(e[0], t); v[8]  = csub(e[0], t);
    t = cmulw(o[1], C1, (float)S * C3);     v[1] = cadd(e[1], t); v[9]  = csub(e[1], t);
    t = cmulw(o[2], C2, (float)S * C2);     v[2] = cadd(e[2], t); v[10] = csub(e[2], t);
    t = cmulw(o[3], C3, (float)S * C1);     v[3] = cadd(e[3], t); v[11] = csub(e[3], t);
    t = mul_iS<S>(o[4]);                    v[4] = cadd(e[4], t); v[12] = csub(e[4], t);
    t = cmulw(o[5], -C3, (float)S * C1);    v[5] = cadd(e[5], t); v[13] = csub(e[5], t);
    t = cmulw(o[6], -C2, (float)S * C2);    v[6] = cadd(e[6], t); v[14] = csub(e[6], t);
    t = cmulw(o[7], -C1, (float)S * C3);    v[7] = cadd(e[7], t); v[15] = csub(e[7], t);
}

// Log-depth twiddle tree (depth 4).
template <int S>
__device__ __forceinline__ void twiddle16(float2 v[16], int p, float ninv) {
    float th = (float)S * 6.28318530717958647692f * (float)p * ninv;
    float s1, c1; __sincosf(th, &s1, &c1);
    float s8, c8; __sincosf(8.0f * th, &s8, &c8);
    float2 w1 = make_float2(c1, s1);
    float2 w8 = make_float2(c8, s8);
    float2 w2 = cmul(w1, w1);
    v[1] = cmul(v[1], w1);
    v[2] = cmul(v[2], w2);
    float2 w3 = cmul(w2, w1);  v[3] = cmul(v[3], w3);
    float2 w4 = cmul(w2, w2);  v[4] = cmul(v[4], w4);
    float2 w5 = cmul(w3, w2);  v[5] = cmul(v[5], w5);
    float2 w6 = cmul(w4, w2);  v[6] = cmul(v[6], w6);
    float2 w7 = cmul(w5, w2);  v[7] = cmul(v[7], w7);
    v[8] = cmul(v[8], w8);
    float2 w9  = cmul(w8, w1);   v[9]  = cmul(v[9],  w9);
    float2 w10 = cmul(w8, w2);   v[10] = cmul(v[10], w10);
    float2 w11 = cmul(w9, w2);   v[11] = cmul(v[11], w11);
    float2 w12 = cmul(w10, w2);  v[12] = cmul(v[12], w12);
    float2 w13 = cmul(w11, w2);  v[13] = cmul(v[13], w13);
    float2 w14 = cmul(w12, w2);  v[14] = cmul(v[14], w14);
    float2 w15 = cmul(w13, w2);  v[15] = cmul(v[15], w15);
}

// Stage 0 exchange on a padded buffer: float4 writes at p2(16t+r) (pairs are
// contiguous: p2(16t+2j) = 18t+2j, even), read p2(t+256r) = t+2(t>>4)+288r.
template <int S>
__device__ __forceinline__ void stage0_ex(float2 v[16], float2* buf, int t) {
    dft16<S>(v);
    twiddle16<S>(v, t, 1.0f / 4096.0f);
    float4* b4 = (float4*)buf;
    #pragma unroll
    for (int j = 0; j < 8; ++j)
        b4[9 * t + j] = make_float4(v[2 * j].x, v[2 * j].y,
                                    v[2 * j + 1].x, v[2 * j + 1].y);
    __syncthreads();
    const int rb = t + 2 * (t >> 4);
    #pragma unroll
    for (int r = 0; r < 16; ++r) v[r] = buf[rb + 288 * r];
}

// Stage 1 exchange, UNPADDED addressing (write q+256p+16r and read t+256r are
// both conflict-free without padding). Works in any buffer with >=4096 slots.
template <int S>
__device__ __forceinline__ void stage1_ex(float2 v[16], float2* buf, int t) {
    dft16<S>(v);
    twiddle16<S>(v, t >> 4, 1.0f / 256.0f);
    const int base = (t & 15) + 256 * (t >> 4);
    #pragma unroll
    for (int r = 0; r < 16; ++r) buf[base + 16 * r] = v[r];
    __syncthreads();
    #pragma unroll
    for (int r = 0; r < 16; ++r) v[r] = buf[t + 256 * r];
}

__device__ __forceinline__ void cp_async16(uint32_t saddr, const float* gaddr) {
    asm volatile("cp.async.cg.shared.global [%0], [%1], 16;"
                 :: "r"(saddr), "l"(gaddr));
}

extern __shared__ float2 g_smem[];

__global__ void __launch_bounds__(NT, 2)
circconv7_kernel(const float* __restrict__ A, const float* __restrict__ B,
                 float* __restrict__ out) {
    float2* bufA = g_smem;               // padded, 4608 slots
    float2* bufB = g_smem + 4608;        // padded, 4608 slots
    float2* bufC = g_smem + 9216;        // raw, 4096 slots (b prefetch / E1 / Z2)

    const int t = threadIdx.x;
    const size_t row0 = 2 * (size_t)blockIdx.x;
    const float* a1 = A + row0 * NFFT;
    const float* a2 = a1 + NFFT;
    const float* b1 = B + row0 * NFFT;
    const float* b2 = b1 + NFFT;

    float2 v[16];

    // a-loads first (critical path), then prefetch b rows into bufC.
    #pragma unroll
    for (int r = 0; r < 16; ++r) {
        const int k = t + NT * r;
        v[r] = make_float2(a1[k], a2[k]);
    }
    {
        uint32_t cbase;
        asm("{ .reg .u64 u; cvta.to.shared.u64 u, %1; cvt.u32.u64 %0, u; }"
            : "=r"(cbase) : "l"(bufC));
        #pragma unroll
        for (int j = 0; j < 4; ++j) {
            const int fo = 4 * t + 1024 * j;
            cp_async16(cbase + 4u * fo, b1 + fo);            // floats [0..4095]
            cp_async16(cbase + 4u * (fo + 4096), b2 + fo);   // floats [4096..8191]
        }
        asm volatile("cp.async.commit_group;");
    }

    // ---- forward FFT of z1 = a1 + i*a2 ----
    stage0_ex<-1>(v, bufA, t);   // sync #1
    stage1_ex<-1>(v, bufB, t);   // sync #2
    dft16<-1>(v);                // Z1 in regs, natural order k = t+256r

    // Store Z1 to bufA (all bufA E0-reads done before sync #2).
    const int rbA = t + 2 * (t >> 4);
    #pragma unroll
    for (int r = 0; r < 16; ++r) bufA[rbA + 288 * r] = v[r];

    // ---- forward FFT of z2 = b1 + i*b2 from prefetched smem ----
    asm volatile("cp.async.wait_group 0;" ::: "memory");
    __syncthreads();             // sync #3: b data + Z1 store visible
    {
        const float* bc = (const float*)bufC;
        #pragma unroll
        for (int r = 0; r < 16; ++r) {
            const int k = t + NT * r;
            v[r] = make_float2(bc[k], bc[k + NFFT]);
        }
    }
    stage0_ex<-1>(v, bufB, t);   // sync #4 (bufB E1-reads done before sync #3)
    stage1_ex<-1>(v, bufC, t);   // sync #5 (bufC input reads done before sync #4)
    dft16<-1>(v);                // Z2 in regs

    // Store Z2 to bufC: each thread overwrites exactly the slots it just read
    // in stage1_ex (t+256r) -> own-slot overwrite, no barrier needed.
    #pragma unroll
    for (int r = 0; r < 16; ++r) bufC[t + 256 * r] = v[r];
    __syncthreads();             // sync #6: Z2 visible

    // ---- unpack + pointwise multiply (0.5 factors folded into final scale) ----
    #pragma unroll
    for (int r = 0; r < 16; ++r) {
        const int k = t + NT * r;
        const int nk = (NFFT - k) & (NFFT - 1);
        const float2 Z2k = v[r];
        const float2 Z1k = bufA[p2(k)];
        const float2 Z1n = bufA[p2(nk)];
        const float2 Z2n = bufC[nk];
        float2 A1 = make_float2(Z1k.x + Z1n.x, Z1k.y - Z1n.y);
        float2 A2 = make_float2(Z1k.y + Z1n.y, Z1n.x - Z1k.x);
        float2 B1 = make_float2(Z2k.x + Z2n.x, Z2k.y - Z2n.y);
        float2 B2 = make_float2(Z2k.y + Z2n.y, Z2n.x - Z2k.x);
        float2 C1 = cmul(A1, B1);
        float2 C2 = cmul(A2, B2);
        v[r] = make_float2(C1.x - C2.y, C1.y + C2.x);
    }

    // ---- inverse FFT ----
    // E0 -> bufB: last read at fwd2-E0 (before sync #5) -> no pre-write hazard.
    stage0_ex<1>(v, bufB, t);    // sync #7; its post-write sync also means all
                                 // threads passed the unpack (bufA/bufC reads)
    // E1 -> bufA, unpadded addressing (Z1 dead now).
    stage1_ex<1>(v, bufA, t);    // sync #8
    dft16<1>(v);                 // Re = conv(a1,b1), Im = conv(a2,b2)

    float* o1 = out + row0 * NFFT;
    float* o2 = o1 + NFFT;
    const float inv = 1.0f / 16384.0f;  // 1/(4*4096): unpack halves folded in
    #pragma unroll
    for (int r = 0; r < 16; ++r) {
        const int k = t + NT * r;
        o1[k] = v[r].x * inv;
        o2[k] = v[r].y * inv;
    }
}

extern "C" void kernel_launch(void* const* d_in, const int* in_sizes, int n_in,
                              void* d_out, int out_size) {
    const float* a = (const float*)d_in[0];
    const float* b = (const float*)d_in[1];
    float* out = (float*)d_out;

    const int rows = in_sizes[0] / NFFT;  // 8192
    const int nblocks = rows / 2;         // 4096
    // (4608 + 4608 + 4096) float2 = 106496 B; 2 CTAs/SM fit in 228 KB.
    const size_t smem_bytes = (4608 + 4608 + 4096) * sizeof(float2);

    cudaFuncSetAttribute(circconv7_kernel,
                         cudaFuncAttributeMaxDynamicSharedMemorySize,
                         (int)smem_bytes);
    circconv7_kernel<<<nblocks, NT, smem_bytes>>>(a, b, out);
}